// round 12
// baseline (speedup 1.0000x reference)
#include <cuda_runtime.h>

#define LSEQ 768
#define NSEQ 256
#define MD   256
#define MSAD 23
#define SEQD 22
#define ZD   128
#define NB   14
#define RC   32
#define RPAD 24       // floats per msa row in smem (23 + 1 pad, 8B-aligned rows)

// Scratch: kb[i,:] = seq@Wk + bk + bpos  (384 KB)
__device__ float g_kb[LSEQ * ZD];

// ---- packed f32x2 helpers (sm_103a, PTX-only) ----
typedef unsigned long long ull;
__device__ __forceinline__ ull pk2(float a, float b) {
    ull r; asm("mov.b64 %0, {%1, %2};" : "=l"(r) : "f"(a), "f"(b)); return r;
}
__device__ __forceinline__ float hsum2(ull v) {
    float lo, hi;
    asm("mov.b64 {%0, %1}, %2;" : "=f"(lo), "=f"(hi) : "l"(v));
    return lo + hi;
}
__device__ __forceinline__ ull fma2(ull a, ull b, ull c) {
    ull d; asm("fma.rn.f32x2 %0, %1, %2, %3;" : "=l"(d) : "l"(a), "l"(b), "l"(c));
    return d;
}
__device__ __forceinline__ ull add2(ull a, ull b) {
    ull d; asm("add.rn.f32x2 %0, %1, %2;" : "=l"(d) : "l"(a), "l"(b)); return d;
}
__device__ __forceinline__ void st2cs(float* p, ull a, ull b) {
    asm volatile("st.global.cs.v2.u64 [%0], {%1, %2};" :: "l"(p), "l"(a), "l"(b) : "memory");
}
__device__ __forceinline__ void st4cs(float* p, float x, float y, float z, float w) {
    asm volatile("st.global.cs.v4.f32 [%0], {%1, %2, %3, %4};"
                 :: "l"(p), "f"(x), "f"(y), "f"(z), "f"(w) : "memory");
}
__device__ __forceinline__ float4 ld4(const float* p) {
    return *reinterpret_cast<const float4*>(p);
}
__device__ __forceinline__ unsigned smem_u32(const void* p) {
    unsigned a;
    asm("{ .reg .u64 t; cvta.to.shared.u64 t, %1; cvt.u32.u64 %0, t; }" : "=r"(a) : "l"(p));
    return a;
}
__device__ __forceinline__ void cpasync4(unsigned dst, const float* src) {
    asm volatile("cp.async.ca.shared.global [%0], [%1], 4;" :: "r"(dst), "l"(src));
}

// ---------------------------------------------------------------------------
// kb precompute: 2 rows per 256-thread block.
// ---------------------------------------------------------------------------
__global__ __launch_bounds__(256) void kbkern(
    const float* __restrict__ seq, const float* __restrict__ Wk,
    const float* __restrict__ bk,  const float* __restrict__ bpos)
{
    const int tid = threadIdx.x;
    const int rr  = tid >> 7;
    const int c   = tid & 127;
    const int i   = blockIdx.x * 2 + rr;

    __shared__ float s[2][SEQD];
    if (tid < 2 * SEQD)
        s[tid / SEQD][tid % SEQD] = seq[(blockIdx.x * 2 + tid / SEQD) * SEQD + tid % SEQD];
    __syncthreads();

    float a = bk[c] + bpos[c];
    #pragma unroll
    for (int d = 0; d < SEQD; d++) a += s[rr][d] * Wk[d * ZD + c];
    g_kb[i * ZD + c] = a;
}

// constant-rel z segment: o = const + kb[i], batched x8 for MLP
__device__ __forceinline__ void zconst(int ia, int ib, int c, int j,
                                       ull k01, ull k23, float* __restrict__ outz)
{
    const long zs = (long)LSEQ * ZD;
    int i = ia;
    for (; i + 8 <= ib; i += 8) {
        ulonglong2 kv[8];
        #pragma unroll
        for (int u = 0; u < 8; u++)
            kv[u] = *reinterpret_cast<const ulonglong2*>(&g_kb[(i + u) * ZD + c]);
        #pragma unroll
        for (int u = 0; u < 8; u++)
            st2cs(&outz[(i + u) * zs + (long)j * ZD + c],
                  add2(k01, kv[u].x), add2(k23, kv[u].y));
    }
    for (; i < ib; i++) {
        const ulonglong2 kv = *reinterpret_cast<const ulonglong2*>(&g_kb[i * ZD + c]);
        st2cs(&outz[i * zs + (long)j * ZD + c], add2(k01, kv.x), add2(k23, kv.y));
    }
}

// ---------------------------------------------------------------------------
// Fused main kernel: 1536 blocks x 128 threads.
//   g = b>>2; g even -> m-path, g odd -> z-path; rank = (g>>1)*4 + (b&3).
// ---------------------------------------------------------------------------
__global__ __launch_bounds__(128, 4) void mainkern(
    const float* __restrict__ seq,  const float* __restrict__ msa,
    const float* __restrict__ Wmsa, const float* __restrict__ bmsa,
    const float* __restrict__ Ws,   const float* __restrict__ bs,
    const float* __restrict__ Wq,   const float* __restrict__ bq,
    const float* __restrict__ Wpos, const float* __restrict__ Wpos2,
    const float* __restrict__ bpos2,
    float* __restrict__ outm, float* __restrict__ outz)
{
    const int b    = blockIdx.x;
    const int tid  = threadIdx.x;
    const int grp  = b >> 2;
    const int rank = (grp >> 1) * 4 + (b & 3);   // 0..767 within type

    if (grp & 1) {
        // ------------- z-path: z[i,j,:] = sq[j] + kb[i] + Wpos[rel] ---------
        const int zid = rank;
        const int j   = (zid >> 2) * 4 + (tid >> 5);
        const int iq  = zid & 3;
        const int c   = (tid & 31) * 4;

        float4 q;
        q.x = bq[c]; q.y = bq[c + 1]; q.z = bq[c + 2]; q.w = bq[c + 3];
        #pragma unroll
        for (int d = 0; d < SEQD; d++) {
            const float  sv = seq[j * SEQD + d];
            const float4 w  = ld4(Wq + d * ZD + c);
            q.x += sv * w.x; q.y += sv * w.y; q.z += sv * w.z; q.w += sv * w.w;
        }
        const ull q01 = pk2(q.x, q.y);
        const ull q23 = pk2(q.z, q.w);

        const ulonglong2 wpHI = *reinterpret_cast<const ulonglong2*>(&Wpos[64 * ZD + c]);
        const ulonglong2 wpLO = *reinterpret_cast<const ulonglong2*>(&Wpos[c]);
        const ull hi01 = add2(q01, wpHI.x), hi23 = add2(q23, wpHI.y);
        const ull lo01 = add2(q01, wpLO.x), lo23 = add2(q23, wpLO.y);

        const int i0   = iq * (LSEQ / 4);
        const int iend = i0 + LSEQ / 4;
        const int sA   = min(max(j - 32, i0), iend);
        const int sB   = min(max(j + 33, i0), iend);

        zconst(i0, sA, c, j, hi01, hi23, outz);

        const long zs = (long)LSEQ * ZD;
        #pragma unroll 2
        for (int i = sA; i < sB; i++) {
            const int rel = j - i + RC;
            const ulonglong2 kv = *reinterpret_cast<const ulonglong2*>(&g_kb[i * ZD + c]);
            const ulonglong2 wp = *reinterpret_cast<const ulonglong2*>(&Wpos[rel * ZD + c]);
            st2cs(&outz[i * zs + (long)j * ZD + c],
                  add2(add2(q01, kv.x), wp.x), add2(add2(q23, kv.y), wp.y));
        }

        zconst(sB, iend, c, j, lo01, lo23, outz);
        return;
    }

    // ------------ m-path: m[n,l,:] = msa[n,l,:]@Wmsa + sp[l,:] --------------
    // k-pair lanes: acc2_c = sum_t {m[r,2t]*W[2t,c], m[r,2t+1]*W[2t+1,c]},
    // final = hsum(acc2) + m[r,22]*W[22,c]. LDS.64 is a DIRECT fma2 operand.
    const int l  = rank;
    const int rg = tid >> 6;              // 0..1
    const int c  = (tid & 63) * 4;

    __shared__ float rows[NSEQ][RPAD];    // natural row-major, 24.6 KB
    __shared__ float srow[SEQD];

    if (tid < SEQD) srow[tid] = seq[l * SEQD + tid];
    for (int idx = tid; idx < NSEQ * MSAD; idx += 128) {
        const int n = idx / MSAD;
        const int k = idx - n * MSAD;
        cpasync4(smem_u32(&rows[n][k]), &msa[(n * LSEQ + l) * MSAD + k]);
    }
    asm volatile("cp.async.commit_group;" ::: "memory");

    // per-thread weights: k-pair packed per channel (88 regs) + k=22 row
    ull wA[11], wB[11], wC[11], wD[11];
    #pragma unroll
    for (int t = 0; t < 11; t++) {
        const float4 we = ld4(Wmsa + (2 * t) * MD + c);
        const float4 wo = ld4(Wmsa + (2 * t + 1) * MD + c);
        wA[t] = pk2(we.x, wo.x);
        wB[t] = pk2(we.y, wo.y);
        wC[t] = pk2(we.z, wo.z);
        wD[t] = pk2(we.w, wo.w);
    }
    const float4 w22 = ld4(Wmsa + 22 * MD + c);

    // sp[l, c..c+3]
    float4 sp;
    sp.x = bs[c]     + bpos2[c]     + bmsa[c];
    sp.y = bs[c + 1] + bpos2[c + 1] + bmsa[c + 1];
    sp.z = bs[c + 2] + bpos2[c + 2] + bmsa[c + 2];
    sp.w = bs[c + 3] + bpos2[c + 3] + bmsa[c + 3];
    #pragma unroll
    for (int bb = 0; bb < NB; bb++)
        if ((l >> bb) & 1) {
            const float4 w = ld4(Wpos2 + bb * MD + c);
            sp.x += w.x; sp.y += w.y; sp.z += w.z; sp.w += w.w;
        }
    asm volatile("cp.async.wait_group 0;" ::: "memory");
    __syncthreads();
    #pragma unroll
    for (int d = 0; d < SEQD; d++) {
        const float  sv = srow[d];
        const float4 w  = ld4(Ws + d * MD + c);
        sp.x += sv * w.x; sp.y += sv * w.y; sp.z += sv * w.z; sp.w += sv * w.w;
    }
    const ull spx = pk2(sp.x, 0.0f);
    const ull spy = pk2(sp.y, 0.0f);
    const ull spz = pk2(sp.z, 0.0f);
    const ull spw = pk2(sp.w, 0.0f);

    // main loop: one row-pair per iteration, 8 chains of depth 11, zero movs
    for (int it = 0; it < NSEQ / 4; it++) {
        const int p  = it * 2 + rg;       // pair index 0..127
        const int na = p * 2;
        const float* r0 = rows[na];
        const float* r1 = rows[na + 1];

        ull a0 = spx, a1 = spy, a2 = spz, a3 = spw;   // row na
        ull b0 = spx, b1 = spy, b2 = spz, b3 = spw;   // row na+1
        #pragma unroll
        for (int t = 0; t < 11; t++) {
            const ull va = *reinterpret_cast<const ull*>(r0 + 2 * t);  // LDS.64
            const ull vb = *reinterpret_cast<const ull*>(r1 + 2 * t);
            a0 = fma2(wA[t], va, a0); a1 = fma2(wB[t], va, a1);
            a2 = fma2(wC[t], va, a2); a3 = fma2(wD[t], va, a3);
            b0 = fma2(wA[t], vb, b0); b1 = fma2(wB[t], vb, b1);
            b2 = fma2(wC[t], vb, b2); b3 = fma2(wD[t], vb, b3);
        }
        const float m22a = r0[22];
        const float m22b = r1[22];

        float* oa = &outm[((long)na * LSEQ + l) * MD + c];
        float* ob = &outm[((long)(na + 1) * LSEQ + l) * MD + c];
        st4cs(oa,
              fmaf(m22a, w22.x, hsum2(a0)), fmaf(m22a, w22.y, hsum2(a1)),
              fmaf(m22a, w22.z, hsum2(a2)), fmaf(m22a, w22.w, hsum2(a3)));
        st4cs(ob,
              fmaf(m22b, w22.x, hsum2(b0)), fmaf(m22b, w22.y, hsum2(b1)),
              fmaf(m22b, w22.z, hsum2(b2)), fmaf(m22b, w22.w, hsum2(b3)));
    }
}

// ---------------------------------------------------------------------------
extern "C" void kernel_launch(void* const* d_in, const int* in_sizes, int n_in,
                              void* d_out, int out_size)
{
    const float* seq   = (const float*)d_in[0];
    const float* msa   = (const float*)d_in[1];
    const float* Wmsa  = (const float*)d_in[2];
    const float* bmsa  = (const float*)d_in[3];
    const float* Ws    = (const float*)d_in[4];
    const float* bs    = (const float*)d_in[5];
    const float* Wq    = (const float*)d_in[6];
    const float* bq    = (const float*)d_in[7];
    const float* Wk    = (const float*)d_in[8];
    const float* bk    = (const float*)d_in[9];
    const float* Wpos  = (const float*)d_in[10];
    const float* bpos  = (const float*)d_in[11];
    const float* Wpos2 = (const float*)d_in[12];
    const float* bpos2 = (const float*)d_in[13];

    float* outm = (float*)d_out;
    float* outz = outm + (long)NSEQ * LSEQ * MD;

    kbkern<<<LSEQ / 2, 256>>>(seq, Wk, bk, bpos);
    mainkern<<<1536, 128>>>(seq, msa, Wmsa, bmsa, Ws, bs, Wq, bq,
                            Wpos, Wpos2, bpos2, outm, outz);
}